// round 3
// baseline (speedup 1.0000x reference)
#include <cuda_runtime.h>

// SmallRNN: h_t = tanh(x_t * w_ih^T + b_ih + h_{t-1} * w_hh^T + b_hh), out = h_T @ fc_w^T + fc_b
// Shapes: x [B=4096, T=2048, I=1], w_ih [8,1], w_hh [8,8], b_* [8], fc_w [1,8], fc_b [1]
//
// Layout: 8 lanes per batch element (lane j owns h_j). Per step:
//   - gather the group's 8 recurrent values via __shfl_sync(width=8)
//   - two-way FMA tree dot product
//   - tanh via ex2.approx + rcp.approx, with 2*log2(e) pre-folded into weights
//   - we shuffle r = 1/(1+exp(2s)) instead of h = 1-2r, folding the affine map
//     into the weights/bias to shorten the dependency chain by one FMA.

#define TBLOCK 256

__device__ __forceinline__ float ex2f(float x) {
    float y; asm("ex2.approx.f32 %0, %1;" : "=f"(y) : "f"(x)); return y;
}
__device__ __forceinline__ float rcpf(float x) {
    float y; asm("rcp.approx.f32 %0, %1;" : "=f"(y) : "f"(x)); return y;
}

__device__ __forceinline__ void rnn_step(float& r, float xv,
                                         const float w2[8], float Bj, float wihc) {
    // u accumulates 2*log2(e) * (pre-tanh activation)
    float u = fmaf(xv, wihc, Bj);
    float r0 = __shfl_sync(0xffffffffu, r, 0, 8);
    float r1 = __shfl_sync(0xffffffffu, r, 1, 8);
    float r2 = __shfl_sync(0xffffffffu, r, 2, 8);
    float r3 = __shfl_sync(0xffffffffu, r, 3, 8);
    float r4 = __shfl_sync(0xffffffffu, r, 4, 8);
    float r5 = __shfl_sync(0xffffffffu, r, 5, 8);
    float r6 = __shfl_sync(0xffffffffu, r, 6, 8);
    float r7 = __shfl_sync(0xffffffffu, r, 7, 8);
    // two-way split FMA tree to shorten the dependency chain
    float a = fmaf(r0, w2[0], u);
    float b = r1 * w2[1];
    a = fmaf(r2, w2[2], a);
    b = fmaf(r3, w2[3], b);
    a = fmaf(r4, w2[4], a);
    b = fmaf(r5, w2[5], b);
    a = fmaf(r6, w2[6], a);
    b = fmaf(r7, w2[7], b);
    u = a + b;
    // r_new = 1 / (1 + exp(2*s)) = sigmoid(-2s);  h = 1 - 2r (folded into weights)
    float e = ex2f(u);
    r = rcpf(e + 1.0f);
}

__global__ void __launch_bounds__(TBLOCK)
SmallRNN_kernel(const float* __restrict__ x,
                const float* __restrict__ w_ih,
                const float* __restrict__ w_hh,
                const float* __restrict__ b_ih,
                const float* __restrict__ b_hh,
                const float* __restrict__ fc_w,
                const float* __restrict__ fc_b,
                float* __restrict__ out,
                int B, int T) {
    int gtid = blockIdx.x * TBLOCK + threadIdx.x;
    int b_raw = gtid >> 3;     // batch element
    int j = gtid & 7;          // hidden unit owned by this lane
    // keep all lanes active for full-mask shuffles; clamp and guard the store
    int b = (b_raw < B) ? b_raw : (B - 1);

    const float c = 2.8853900817779268f; // 2 * log2(e)

    // Load and transform weights:
    //   s_j = bias_j + wih_j * x + sum_k W[j,k] * h_k,  h_k = 1 - 2*r_k
    //   u_j = c*s_j = Bj + (c*wih_j)*x + sum_k (-2c*W[j,k]) * r_k
    //   Bj  = c * (b_ih + b_hh + sum_k W[j,k])
    float w2[8];
    float rowsum = 0.0f;
#pragma unroll
    for (int k = 0; k < 8; k++) {
        float w = w_hh[j * 8 + k];
        rowsum += w;
        w2[k] = -2.0f * c * w;
    }
    float Bj   = c * (b_ih[j] + b_hh[j] + rowsum);
    float wihc = c * w_ih[j];

    const float* xp = x + (size_t)b * (size_t)T;
    float r = 0.5f; // h0 = 0  ->  r0 = sigmoid(0) = 0.5

    int Tm = T & ~7; // vectorized portion (T=2048 -> all of it)
    if (((unsigned long long)xp & 15ull) == 0ull) {
        float4 xa, xb_;
        if (Tm >= 8) {
            xa  = *(const float4*)(xp);
            xb_ = *(const float4*)(xp + 4);
        }
        for (int t = 0; t < Tm; t += 8) {
            float4 xn0, xn1;
            if (t + 8 < Tm) {
                xn0 = *(const float4*)(xp + t + 8);
                xn1 = *(const float4*)(xp + t + 12);
            } else {
                xn0 = make_float4(0.f, 0.f, 0.f, 0.f);
                xn1 = xn0;
            }
            rnn_step(r, xa.x,  w2, Bj, wihc);
            rnn_step(r, xa.y,  w2, Bj, wihc);
            rnn_step(r, xa.z,  w2, Bj, wihc);
            rnn_step(r, xa.w,  w2, Bj, wihc);
            rnn_step(r, xb_.x, w2, Bj, wihc);
            rnn_step(r, xb_.y, w2, Bj, wihc);
            rnn_step(r, xb_.z, w2, Bj, wihc);
            rnn_step(r, xb_.w, w2, Bj, wihc);
            xa  = xn0;
            xb_ = xn1;
        }
    } else {
        Tm = 0; // unaligned fallback: do everything scalar
    }
    for (int t = Tm; t < T; t++) {
        rnn_step(r, xp[t], w2, Bj, wihc);
    }

    // Final hidden state and FC: out[b] = sum_j h_j * fc_w[j] + fc_b
    float h = fmaf(-2.0f, r, 1.0f);
    float v = h * fc_w[j];
    v += __shfl_xor_sync(0xffffffffu, v, 4, 8);
    v += __shfl_xor_sync(0xffffffffu, v, 2, 8);
    v += __shfl_xor_sync(0xffffffffu, v, 1, 8);
    if (j == 0 && b_raw < B) out[b] = v + fc_b[0];
}

extern "C" void kernel_launch(void* const* d_in, const int* in_sizes, int n_in,
                              void* d_out, int out_size) {
    const float* x    = (const float*)d_in[0];
    const float* w_ih = (const float*)d_in[1];
    const float* w_hh = (const float*)d_in[2];
    const float* b_ih = (const float*)d_in[3];
    const float* b_hh = (const float*)d_in[4];
    const float* fc_w = (const float*)d_in[5];
    const float* fc_b = (const float*)d_in[6];
    float* out = (float*)d_out;

    int B = out_size;                 // O = 1
    int T = in_sizes[0] / B;          // I = 1
    int threads = B * 8;
    int grid = (threads + TBLOCK - 1) / TBLOCK;
    SmallRNN_kernel<<<grid, TBLOCK>>>(x, w_ih, w_hh, b_ih, b_hh, fc_w, fc_b,
                                      out, B, T);
}